// round 16
// baseline (speedup 1.0000x reference)
#include <cuda_runtime.h>
#include <cuda_fp16.h>
#include <math.h>
#include <cstdint>

#define BQ   2
#define SQ   2048
#define DIM  1024
#define HQ   16
#define DH   64
#define GQ   16
#define IQ   256
#define MROW (BQ*SQ)   /* 4096 */

// scores*0.125 folded into Q together with log2(e) so softmax uses raw ex2
#define QSCALE 0.18033688011112042f   /* 0.125 * log2(e) */

// ---------------- device scratch (no allocations allowed) ----------------
__device__ __half g_w1[4][DIM*DIM];   // W_eff fp16, [n][k]
__device__ __half g_a1[MROW*DIM];     // activation fp16 (x / attn out)
__device__ __half g_q1[MROW*DIM];     // Q fp16 (rope+scale applied)
__device__ __half g_k1[MROW*DIM];
__device__ __half g_v1[MROW*DIM];

// ---------------- helpers --------------------------------------------------
__device__ __forceinline__ uint32_t smem_to_u32(const void* p) {
    uint32_t a;
    asm("{ .reg .u64 t; cvta.to.shared.u64 t, %1; cvt.u32.u64 %0, t; }"
        : "=r"(a) : "l"(p));
    return a;
}
__device__ __forceinline__ void cp_async16(uint32_t dst, const void* src) {
    asm volatile("cp.async.ca.shared.global [%0], [%1], 16;"
                 :: "r"(dst), "l"(src));
}
#define CP_COMMIT() asm volatile("cp.async.commit_group;" ::: "memory")
#define CP_WAIT(n)  asm volatile("cp.async.wait_group %0;" :: "n"(n) : "memory")

__device__ __forceinline__ float ex2f(float x) {
    float r;
    asm("ex2.approx.f32 %0, %1;" : "=f"(r) : "f"(x));
    return r;
}
// packed half2 ex2
__device__ __forceinline__ uint32_t ex2h2(uint32_t x) {
    uint32_t r;
    asm("ex2.approx.f16x2 %0, %1;" : "=r"(r) : "r"(x));
    return r;
}

__device__ __forceinline__ uint32_t packf16(float x, float y) {
    __half2 h = __floats2half2_rn(x, y);
    return *reinterpret_cast<uint32_t*>(&h);
}
__device__ __forceinline__ float2 unpackf16(uint32_t v) {
    __half2 h = *reinterpret_cast<__half2*>(&v);
    return __half22float2(h);
}

__device__ __forceinline__ void mma16816h(float* c, const uint32_t* a, const uint32_t* b) {
    asm volatile(
        "mma.sync.aligned.m16n8k16.row.col.f32.f16.f16.f32 "
        "{%0,%1,%2,%3}, {%4,%5,%6,%7}, {%8,%9}, {%0,%1,%2,%3};"
        : "+f"(c[0]), "+f"(c[1]), "+f"(c[2]), "+f"(c[3])
        : "r"(a[0]), "r"(a[1]), "r"(a[2]), "r"(a[3]), "r"(b[0]), "r"(b[1]));
}
__device__ __forceinline__ void ldmatrix_x4(uint32_t* r, uint32_t addr) {
    asm volatile("ldmatrix.sync.aligned.m8n8.x4.shared.b16 {%0,%1,%2,%3}, [%4];"
                 : "=r"(r[0]), "=r"(r[1]), "=r"(r[2]), "=r"(r[3]) : "r"(addr));
}
__device__ __forceinline__ void ldmatrix_x4_trans(uint32_t* r, uint32_t addr) {
    asm volatile("ldmatrix.sync.aligned.m8n8.x4.trans.shared.b16 {%0,%1,%2,%3}, [%4];"
                 : "=r"(r[0]), "=r"(r[1]), "=r"(r[2]), "=r"(r[3]) : "r"(addr));
}

// quaternion rope rotation (reference math, fp32)
__device__ __forceinline__ void qrot(float cs, float sn, int ax,
                                     float xr, float xi, float xj, float xk,
                                     float& pr, float& pi, float& pj, float& pk) {
    float ui = (ax == 0) ? sn : 0.f;
    float uj = (ax == 1) ? sn : 0.f;
    float uk = (ax == 2) ? sn : 0.f;
    pr = cs * xr - ui * xi - uj * xj - uk * xk;
    pi = cs * xi + ui * xr + uj * xk - uk * xj;
    pj = cs * xj - ui * xk + uj * xr + uk * xi;
    pk = cs * xk + ui * xj - uj * xi + uk * xr;
}

// ---------------- build all 4 effective quaternion weights (fp16) ----------
struct WPtrs { const float* w[4][4]; };   // [proj][comp r,i,j,k]
__global__ void build_w_all_kernel(WPtrs wp, __half* __restrict__ WBase) {
    int proj = blockIdx.y;
    int idx = blockIdx.x * blockDim.x + threadIdx.x;   // 0 .. DIM*IQ-1
    int n = idx >> 8;          // 0..1023
    int p = idx & 255;         // 0..255
    int m = n >> 2, c = n & 3;

    int off = m * IQ + p;
    float r = wp.w[proj][0][off], i = wp.w[proj][1][off];
    float j = wp.w[proj][2][off], k = wp.w[proj][3][off];

    float v0, v1, v2, v3;
    switch (c) {
        case 0: v0 =  r; v1 = -i; v2 = -j; v3 = -k; break;
        case 1: v0 =  i; v1 =  r; v2 = -j; v3 =  k; break;
        case 2: v0 =  j; v1 =  i; v2 =  r; v3 = -k; break;
        default: v0 = k; v1 = -i; v2 =  j; v3 =  r; break;
    }

    size_t o = ((size_t)proj * DIM * DIM + (size_t)n * DIM + 4 * p) >> 2;
    ((uint2*)WBase)[o] = make_uint2(packf16(v0, v1), packf16(v2, v3));
}

// ---------------- convert fp32 activation into fp16 -------------------------
__global__ void cvt16_kernel(const float* __restrict__ in,
                             __half* __restrict__ out) {
    int i = blockIdx.x * blockDim.x + threadIdx.x;     // float4 index
    float4 v = ((const float4*)in)[i];
    ((uint2*)out)[i] = make_uint2(packf16(v.x, v.y), packf16(v.z, v.w));
}

// ================= fp16 single-product GEMM core ===========================
// C = A @ B^T, both fp16. Tile 128x128, 8 warps, K-slab 32, double buffered.
// smem per buffer (u32): A@0, B@2560; row stride 20 u32.
#define SMS   20
#define BUFU  5120
#define GEMM_SMEM (2 * BUFU * 4)   /* 40960 */

__device__ __forceinline__ void gemm_core(
    const __half* pA, const __half* pB,
    uint32_t sbase, uint32_t* smu, uint32_t doff0, uint32_t rstep,
    int wm, int wn, int g, int t, float acc[4][4][4]) {

    #define ISSUE_SLAB(s, b) do {                                              \
        int _k0 = (s) * 32;                                                    \
        uint32_t _d = sbase + (uint32_t)(b) * (BUFU * 4) + doff0;              \
        cp_async16(_d,                  pA + _k0);                             \
        cp_async16(_d + rstep,          pA + _k0 + (size_t)64 * DIM);          \
        cp_async16(_d + 2560*4,         pB + _k0);                             \
        cp_async16(_d + 2560*4 + rstep, pB + _k0 + (size_t)64 * DIM);          \
        CP_COMMIT();                                                           \
    } while (0)

    ISSUE_SLAB(0, 0);

    for (int s = 0; s < 32; s++) {
        const int cb = s & 1, nb = cb ^ 1;
        if (s + 1 < 32) {
            ISSUE_SLAB(s + 1, nb);
            CP_WAIT(1);
        } else {
            CP_WAIT(0);
        }
        __syncthreads();

        const uint32_t* base = smu + cb * BUFU;
        #pragma unroll
        for (int kk = 0; kk < 2; kk++) {
            uint32_t a[4][4];
            #pragma unroll
            for (int mi = 0; mi < 4; mi++) {
                int r0 = (wm * 64 + mi * 16 + g) * SMS + kk * 8 + t;
                a[mi][0] = base[r0];     a[mi][1] = base[r0 + 8 * SMS];
                a[mi][2] = base[r0 + 4]; a[mi][3] = base[r0 + 8 * SMS + 4];
            }
            uint32_t bb[4][2];
            #pragma unroll
            for (int nj = 0; nj < 4; nj++) {
                int rn = (wn * 32 + nj * 8 + g) * SMS + kk * 8 + t;
                bb[nj][0] = base[2560 + rn]; bb[nj][1] = base[2560 + rn + 4];
            }
            #pragma unroll
            for (int mi = 0; mi < 4; mi++)
                #pragma unroll
                for (int nj = 0; nj < 4; nj++)
                    mma16816h(acc[mi][nj], a[mi], bb[nj]);
        }
        __syncthreads();
    }
}

// z = 0: Q (rope + scale); 1: K (rope); 2: V (plain). All fp16 out.
__global__ __launch_bounds__(256) void qkv_gemm(
    const __half* __restrict__ A1, const __half* __restrict__ WBase,
    const float* __restrict__ q_b, const float* __restrict__ k_b,
    const float* __restrict__ v_b,
    __half* __restrict__ Q1, __half* __restrict__ K1, __half* __restrict__ V1) {
    extern __shared__ uint32_t smu[];
    const uint32_t sbase = smem_to_u32(smu);
    const int tid  = threadIdx.x;
    const int lane = tid & 31, wid = tid >> 5;
    const int g = lane >> 2, t = lane & 3;
    const int wm = wid & 1, wn = wid >> 1;
    const int bm = blockIdx.y * 128, bn = blockIdx.x * 128;
    const int z = blockIdx.z;

    const __half* B = WBase + (size_t)z * DIM * DIM;
    const float* bias = (z == 0) ? q_b : (z == 1) ? k_b : v_b;
    __half* C = (z == 0) ? Q1 : (z == 1) ? K1 : V1;

    float acc[4][4][4];
    #pragma unroll
    for (int i = 0; i < 4; i++)
        #pragma unroll
        for (int j = 0; j < 4; j++)
            #pragma unroll
            for (int q = 0; q < 4; q++) acc[i][j][q] = 0.f;

    const int crow0 = tid >> 2;
    const int ccol  = tid & 3;
    gemm_core(A1 + (size_t)(bm + crow0) * DIM + ccol * 8,
              B  + (size_t)(bn + crow0) * DIM + ccol * 8,
              sbase, smu,
              (uint32_t)(crow0 * SMS + ccol * 4) * 4,
              (uint32_t)(64 * SMS) * 4,
              wm, wn, g, t, acc);

    if (z == 2) {
        // ---- V: plain fp16 ----
        #pragma unroll
        for (int mi = 0; mi < 4; mi++) {
            int row = bm + wm * 64 + mi * 16 + g;
            #pragma unroll
            for (int nj = 0; nj < 4; nj++) {
                int col = bn + wn * 32 + nj * 8 + 2 * t;
                float bx = bias[col], by = bias[col + 1];
                *(uint32_t*)&C[(size_t)row * DIM + col] =
                    packf16(acc[mi][nj][0] + bx, acc[mi][nj][1] + by);
                *(uint32_t*)&C[(size_t)(row + 8) * DIM + col] =
                    packf16(acc[mi][nj][2] + bx, acc[mi][nj][3] + by);
            }
        }
    } else {
        // ---- Q/K: fused RoPE; Q also folds softmax scale ----
        const bool evn = (t & 1) == 0;
        const float osc = (z == 0) ? QSCALE : 1.0f;
        #pragma unroll
        for (int nj = 0; nj < 4; nj++) {
            int col = bn + wn * 32 + nj * 8 + 2 * t;
            int grp = (col >> 2) & 15;
            float inv = powf(10000.0f, -(float)grp / 16.0f);
            int ax = grp % 3;
            float bx = bias[col], by = bias[col + 1];
            #pragma unroll
            for (int mi = 0; mi < 4; mi++) {
                int row = bm + wm * 64 + mi * 16 + g;
                float v0 = acc[mi][nj][0] + bx, v1 = acc[mi][nj][1] + by;
                float v2 = acc[mi][nj][2] + bx, v3 = acc[mi][nj][3] + by;
                float p0 = __shfl_xor_sync(0xFFFFFFFFu, v0, 1);
                float p1 = __shfl_xor_sync(0xFFFFFFFFu, v1, 1);
                float p2 = __shfl_xor_sync(0xFFFFFFFFu, v2, 1);
                float p3 = __shfl_xor_sync(0xFFFFFFFFu, v3, 1);
                #pragma unroll
                for (int half = 0; half < 2; half++) {
                    int r = row + 8 * half;
                    float a = (float)(r & 2047) * inv;
                    float cs = cosf(a), sn = sinf(a);
                    float a0 = half ? v2 : v0, a1 = half ? v3 : v1;
                    float b0 = half ? p2 : p0, b1 = half ? p3 : p1;
                    float xr, xi, xj, xk;
                    if (evn) { xr = a0; xi = a1; xj = b0; xk = b1; }
                    else     { xr = b0; xi = b1; xj = a0; xk = a1; }
                    float pr, pi, pj, pk;
                    qrot(cs, sn, ax, xr, xi, xj, xk, pr, pi, pj, pk);
                    float o0 = (evn ? pr : pj) * osc, o1 = (evn ? pi : pk) * osc;
                    *(uint32_t*)&C[(size_t)r * DIM + col] = packf16(o0, o1);
                }
            }
        }
    }
}

// ================= O-projection GEMM (fp32 out) ============================
__global__ __launch_bounds__(256) void o_gemm(
    const __half* __restrict__ A1, const __half* __restrict__ B,
    const float* __restrict__ bias, float* __restrict__ C) {
    extern __shared__ uint32_t smu[];
    const uint32_t sbase = smem_to_u32(smu);
    const int tid  = threadIdx.x;
    const int lane = tid & 31, wid = tid >> 5;
    const int g = lane >> 2, t = lane & 3;
    const int wm = wid & 1, wn = wid >> 1;
    const int bm = blockIdx.y * 128, bn = blockIdx.x * 128;

    float acc[4][4][4];
    #pragma unroll
    for (int i = 0; i < 4; i++)
        #pragma unroll
        for (int j = 0; j < 4; j++)
            #pragma unroll
            for (int q = 0; q < 4; q++) acc[i][j][q] = 0.f;

    const int crow0 = tid >> 2;
    const int ccol  = tid & 3;
    gemm_core(A1 + (size_t)(bm + crow0) * DIM + ccol * 8,
              B  + (size_t)(bn + crow0) * DIM + ccol * 8,
              sbase, smu,
              (uint32_t)(crow0 * SMS + ccol * 4) * 4,
              (uint32_t)(64 * SMS) * 4,
              wm, wn, g, t, acc);

    #pragma unroll
    for (int mi = 0; mi < 4; mi++) {
        int row = bm + wm * 64 + mi * 16 + g;
        #pragma unroll
        for (int nj = 0; nj < 4; nj++) {
            int col = bn + wn * 32 + nj * 8 + 2 * t;
            float bx = bias[col], by = bias[col + 1];
            float2 v;
            v.x = acc[mi][nj][0] + bx; v.y = acc[mi][nj][1] + by;
            *(float2*)&C[(size_t)row * DIM + col] = v;
            v.x = acc[mi][nj][2] + bx; v.y = acc[mi][nj][3] + by;
            *(float2*)&C[(size_t)(row + 8) * DIM + col] = v;
        }
    }
}

// ================= tensor-core causal flash attention ======================
// 128q x 128k staged tiles (two 64k compute halves), 8 warps, fp16 single
// product, 2-stage double buffer, 2 CTAs/SM, x4-batched LDSM, packed f16x2
// softmax exp, warp-uniform lazy Oa rescale.
// Stage (36864B): K(128 rows)@0, V(128 rows)@18432; 144B rows.
#define ATT_STRIDE 144
#define ATT_STAGE  36864
#define ATT_SMEM   (2 * ATT_STAGE)      /* 73728 */
__global__ __launch_bounds__(256, 2) void attn_tc(
    const __half* __restrict__ Q1,
    const __half* __restrict__ K1, const __half* __restrict__ V1,
    __half* __restrict__ O1) {
    extern __shared__ __align__(16) char sm[];
    const uint32_t sb = smem_to_u32(sm);
    const int tid = threadIdx.x, lane = tid & 31, wid = tid >> 5;
    const int g = lane >> 2, t = lane & 3;
    const int qt = (int)gridDim.x - 1 - (int)blockIdx.x;   // heavy blocks first
    const int bh = blockIdx.y;
    const int b = bh >> 4, h = bh & 15;
    const int qb = qt * 128;
    const size_t rbase = (size_t)b * SQ;
    const int hoff = h * DH;

    // ---- stage Q tile, extract fragments to regs ----
    #pragma unroll
    for (int i = 0; i < 4; i++) {
        int rem = tid + 256 * i;              // 0..1023
        int r = rem >> 3, c = rem & 7;
        cp_async16(sb + r * ATT_STRIDE + c * 16,
                   Q1 + (rbase + qb + r) * DIM + hoff + c * 8);
    }
    CP_COMMIT(); CP_WAIT(0);
    __syncthreads();

    uint32_t qf[4][4];
    {
        uint32_t abase = sb + (wid * 16 + (lane & 15)) * ATT_STRIDE + (lane >> 4) * 16;
        #pragma unroll
        for (int kc = 0; kc < 4; kc++)
            ldmatrix_x4(qf[kc], abase + kc * 32);
    }
    __syncthreads();

    float Oa[8][4];
    #pragma unroll
    for (int j = 0; j < 8; j++)
        #pragma unroll
        for (int e = 0; e < 4; e++) Oa[j][e] = 0.f;
    float m0 = -1e30f, m1 = -1e30f, l0 = 0.f, l1 = 0.f;
    const int r0 = qb + wid * 16 + g;
    const int nt128 = qt + 1;                  // 128-key tiles

    const __half* kvK = K1 + rbase * DIM + hoff;
    const __half* kvV = V1 + rbase * DIM + hoff;

    // issue one 128-key K/V stage (128 rows each)
    #define ISSUE_KV(jt_, st_) do {                                             \
        int _kb = (jt_) * 128;                                                  \
        uint32_t _s = sb + (uint32_t)(st_) * ATT_STAGE;                         \
        _Pragma("unroll")                                                       \
        for (int i = 0; i < 8; i++) {                                           \
            int rem = tid + 256 * (i & 3);                                      \
            int r = rem >> 3, c = rem & 7;                                      \
            const __half* src = (i >> 2) == 0 ? kvK : kvV;                      \
            cp_async16(_s + (i >> 2) * 18432 + r * ATT_STRIDE + c * 16,         \
                       src + (size_t)(_kb + r) * DIM + c * 8);                  \
        }                                                                       \
        CP_COMMIT();                                                            \
    } while (0)

    ISSUE_KV(0, 0);

    // lane sub-addresses for x4 K / x4-trans V loads (2 j per LDSM)
    const uint32_t krow = (uint32_t)((lane & 7) + ((lane >> 4) << 3));
    const uint32_t kcolh = (uint32_t)(((lane >> 3) & 1) * 16);
    const uint32_t vrow = (uint32_t)((lane & 7) + (((lane >> 3) & 1) << 3));
    const uint32_t vcol = (uint32_t)((lane >> 4) & 1);

    for (int jt = 0; jt < nt128; jt++) {
        const int cb = jt & 1, nb = cb ^ 1;
        if (jt + 1 < nt128) {
            ISSUE_KV(jt + 1, nb);
            CP_WAIT(1);
        } else {
            CP_WAIT(0);
        }
        __syncthreads();
        const uint32_t stg = sb + (uint32_t)cb * ATT_STAGE;

        #pragma unroll
        for (int half = 0; half < 2; half++) {
            const int kb = jt * 128 + half * 64;
            const uint32_t hrow = (uint32_t)(half * 64);

            // ---- S = Q K^T : single product, x4 K loads (j pairs) ----
            float S[8][4];
            #pragma unroll
            for (int j = 0; j < 8; j++)
                #pragma unroll
                for (int e = 0; e < 4; e++) S[j][e] = 0.f;

            #pragma unroll
            for (int kc = 0; kc < 4; kc++) {
                uint32_t kaddr = stg + (hrow + krow) * ATT_STRIDE + kc * 32 + kcolh;
                #pragma unroll
                for (int j = 0; j < 8; j += 2) {
                    uint32_t bk[4];
                    ldmatrix_x4(bk, kaddr + j * 8 * ATT_STRIDE);
                    mma16816h(S[j],     qf[kc], bk + 0);
                    mma16816h(S[j + 1], qf[kc], bk + 2);
                }
            }

            // ---- causal mask (S already scaled via Q) ----
            if (kb + 63 > qb) {
                #pragma unroll
                for (int j = 0; j < 8; j++) {
                    int k0 = kb + 8 * j + 2 * t;
                    if (k0     > r0    ) S[j][0] = -1e30f;
                    if (k0 + 1 > r0    ) S[j][1] = -1e30f;
                    if (k0     > r0 + 8) S[j][2] = -1e30f;
                    if (k0 + 1 > r0 + 8) S[j][3] = -1e30f;
                }
            }

            // ---- online softmax (log2 domain), packed f16x2 exp ----
            float tm0 = -1e30f, tm1 = -1e30f;
            #pragma unroll
            for (int j = 0; j < 8; j++) {
                tm0 = fmaxf(tm0, fmaxf(S[j][0], S[j][1]));
                tm1 = fmaxf(tm1, fmaxf(S[j][2], S[j][3]));
            }
            tm0 = fmaxf(tm0, __shfl_xor_sync(0xFFFFFFFFu, tm0, 1));
            tm0 = fmaxf(tm0, __shfl_xor_sync(0xFFFFFFFFu, tm0, 2));
            tm1 = fmaxf(tm1, __shfl_xor_sync(0xFFFFFFFFu, tm1, 1));
            tm1 = fmaxf(tm1, __shfl_xor_sync(0xFFFFFFFFu, tm1, 2));
            float mn0 = fmaxf(m0, tm0), mn1 = fmaxf(m1, tm1);
            float sc0 = ex2f(m0 - mn0), sc1 = ex2f(m1 - mn1);
            m0 = mn0; m1 = mn1;
            l0 *= sc0; l1 *= sc1;
            // warp-uniform lazy rescale: skip 32 FMULs when no lane's max moved
            if (__any_sync(0xFFFFFFFFu, (sc0 != 1.f) | (sc1 != 1.f))) {
                #pragma unroll
                for (int j = 0; j < 8; j++) {
                    Oa[j][0] *= sc0; Oa[j][1] *= sc0;
                    Oa[j][2] *= sc1; Oa[j][3] *= sc1;
                }
            }

            uint32_t P2[8][2];
            #pragma unroll
            for (int j = 0; j < 8; j++) {
                P2[j][0] = ex2h2(packf16(S[j][0] - mn0, S[j][1] - mn0));
                P2[j][1] = ex2h2(packf16(S[j][2] - mn1, S[j][3] - mn1));
                float2 f0 = unpackf16(P2[j][0]);
                float2 f1 = unpackf16(P2[j][1]);
                l0 += f0.x + f0.y;
                l1 += f1.x + f1.y;
            }

            // ---- O += P V : single product, x4-trans V loads (j pairs) ----
            #pragma unroll
            for (int c = 0; c < 4; c++) {
                uint32_t pa[4];
                pa[0] = P2[2*c  ][0];
                pa[1] = P2[2*c  ][1];
                pa[2] = P2[2*c+1][0];
                pa[3] = P2[2*c+1][1];
                uint32_t vbase = stg + 18432 + (hrow + 16 * c + vrow) * ATT_STRIDE;
                #pragma unroll
                for (int j = 0; j < 8; j += 2) {
                    uint32_t bv[4];
                    ldmatrix_x4_trans(bv, vbase + (j + vcol) * 16);
                    mma16816h(Oa[j],     pa, bv + 0);
                    mma16816h(Oa[j + 1], pa, bv + 2);
                }
            }
        }
        __syncthreads();
    }

    // ---- finalize: write fp16 ----
    l0 += __shfl_xor_sync(0xFFFFFFFFu, l0, 1);
    l0 += __shfl_xor_sync(0xFFFFFFFFu, l0, 2);
    l1 += __shfl_xor_sync(0xFFFFFFFFu, l1, 1);
    l1 += __shfl_xor_sync(0xFFFFFFFFu, l1, 2);
    float inv0 = 1.f / l0, inv1 = 1.f / l1;
    size_t off0 = (rbase + r0) * DIM + hoff + 2 * t;
    size_t off1 = (rbase + r0 + 8) * DIM + hoff + 2 * t;
    #pragma unroll
    for (int j = 0; j < 8; j++) {
        *(uint32_t*)&O1[off0 + 8 * j] = packf16(Oa[j][0] * inv0, Oa[j][1] * inv0);
        *(uint32_t*)&O1[off1 + 8 * j] = packf16(Oa[j][2] * inv1, Oa[j][3] * inv1);
    }
}

// ---------------- launch ---------------------------------------------------
extern "C" void kernel_launch(void* const* d_in, const int* in_sizes, int n_in,
                              void* d_out, int out_size) {
    const float* x = (const float*)d_in[0];
    // d_in[1] = mask (pure causal triu, ignored)
    const float* q_b = (const float*)d_in[6];
    const float* k_b = (const float*)d_in[11];
    const float* v_b = (const float*)d_in[16];
    const float* o_b = (const float*)d_in[21];

    WPtrs wp;
    for (int pr = 0; pr < 4; pr++)
        for (int cm = 0; cm < 4; cm++)
            wp.w[pr][cm] = (const float*)d_in[2 + 5 * pr + cm];

    __half *w1, *a1, *q1, *k1, *v1;
    cudaGetSymbolAddress((void**)&w1, g_w1);
    cudaGetSymbolAddress((void**)&a1, g_a1);
    cudaGetSymbolAddress((void**)&q1, g_q1);
    cudaGetSymbolAddress((void**)&k1, g_k1);
    cudaGetSymbolAddress((void**)&v1, g_v1);

    cudaFuncSetAttribute(qkv_gemm, cudaFuncAttributeMaxDynamicSharedMemorySize,
                         GEMM_SMEM);
    cudaFuncSetAttribute(o_gemm, cudaFuncAttributeMaxDynamicSharedMemorySize,
                         GEMM_SMEM);
    cudaFuncSetAttribute(attn_tc, cudaFuncAttributeMaxDynamicSharedMemorySize,
                         ATT_SMEM);

    dim3 wgrid((DIM * IQ) / 256, 4);
    build_w_all_kernel<<<wgrid, 256>>>(wp, w1);

    const int sblocks = (MROW * DIM / 4) / 256;
    cvt16_kernel<<<sblocks, 256>>>(x, a1);

    dim3 qkvgrid(DIM / 128, MROW / 128, 3);    // (8, 32, 3)
    qkv_gemm<<<qkvgrid, 256, GEMM_SMEM>>>(a1, w1, q_b, k_b, v_b, q1, k1, v1);

    dim3 agrid(SQ / 128, BQ * HQ);             // (16, 32)
    attn_tc<<<agrid, 256, ATT_SMEM>>>(q1, k1, v1, a1);

    dim3 ogrid(DIM / 128, MROW / 128);         // (8, 32)
    o_gemm<<<ogrid, 256, GEMM_SMEM>>>(a1, w1 + 3 * (size_t)DIM * DIM,
                                      o_b, (float*)d_out);
}

// round 17
// speedup vs baseline: 1.1381x; 1.1381x over previous
#include <cuda_runtime.h>
#include <cuda_fp16.h>
#include <math.h>
#include <cstdint>

#define BQ   2
#define SQ   2048
#define DIM  1024
#define HQ   16
#define DH   64
#define GQ   16
#define IQ   256
#define MROW (BQ*SQ)   /* 4096 */

// scores*0.125 folded into Q together with log2(e) so softmax uses raw ex2
#define QSCALE 0.18033688011112042f   /* 0.125 * log2(e) */

// ---------------- device scratch (no allocations allowed) ----------------
__device__ __half g_w1[4][DIM*DIM];   // W_eff fp16, [n][k]
__device__ __half g_a1[MROW*DIM];     // activation fp16 (x / attn out)
__device__ __half g_q1[MROW*DIM];     // Q fp16 (rope+scale applied)
__device__ __half g_k1[MROW*DIM];
__device__ __half g_v1[MROW*DIM];

// ---------------- helpers --------------------------------------------------
__device__ __forceinline__ uint32_t smem_to_u32(const void* p) {
    uint32_t a;
    asm("{ .reg .u64 t; cvta.to.shared.u64 t, %1; cvt.u32.u64 %0, t; }"
        : "=r"(a) : "l"(p));
    return a;
}
__device__ __forceinline__ void cp_async16(uint32_t dst, const void* src) {
    asm volatile("cp.async.ca.shared.global [%0], [%1], 16;"
                 :: "r"(dst), "l"(src));
}
#define CP_COMMIT() asm volatile("cp.async.commit_group;" ::: "memory")
#define CP_WAIT(n)  asm volatile("cp.async.wait_group %0;" :: "n"(n) : "memory")

__device__ __forceinline__ float ex2f(float x) {
    float r;
    asm("ex2.approx.f32 %0, %1;" : "=f"(r) : "f"(x));
    return r;
}
// packed half2 ex2
__device__ __forceinline__ uint32_t ex2h2(uint32_t x) {
    uint32_t r;
    asm("ex2.approx.f16x2 %0, %1;" : "=r"(r) : "r"(x));
    return r;
}

__device__ __forceinline__ uint32_t packf16(float x, float y) {
    __half2 h = __floats2half2_rn(x, y);
    return *reinterpret_cast<uint32_t*>(&h);
}
__device__ __forceinline__ float2 unpackf16(uint32_t v) {
    __half2 h = *reinterpret_cast<__half2*>(&v);
    return __half22float2(h);
}

__device__ __forceinline__ void mma16816h(float* c, const uint32_t* a, const uint32_t* b) {
    asm volatile(
        "mma.sync.aligned.m16n8k16.row.col.f32.f16.f16.f32 "
        "{%0,%1,%2,%3}, {%4,%5,%6,%7}, {%8,%9}, {%0,%1,%2,%3};"
        : "+f"(c[0]), "+f"(c[1]), "+f"(c[2]), "+f"(c[3])
        : "r"(a[0]), "r"(a[1]), "r"(a[2]), "r"(a[3]), "r"(b[0]), "r"(b[1]));
}
__device__ __forceinline__ void ldmatrix_x4(uint32_t* r, uint32_t addr) {
    asm volatile("ldmatrix.sync.aligned.m8n8.x4.shared.b16 {%0,%1,%2,%3}, [%4];"
                 : "=r"(r[0]), "=r"(r[1]), "=r"(r[2]), "=r"(r[3]) : "r"(addr));
}
__device__ __forceinline__ void ldmatrix_x4_trans(uint32_t* r, uint32_t addr) {
    asm volatile("ldmatrix.sync.aligned.m8n8.x4.trans.shared.b16 {%0,%1,%2,%3}, [%4];"
                 : "=r"(r[0]), "=r"(r[1]), "=r"(r[2]), "=r"(r[3]) : "r"(addr));
}

// quaternion rope rotation (reference math, fp32)
__device__ __forceinline__ void qrot(float cs, float sn, int ax,
                                     float xr, float xi, float xj, float xk,
                                     float& pr, float& pi, float& pj, float& pk) {
    float ui = (ax == 0) ? sn : 0.f;
    float uj = (ax == 1) ? sn : 0.f;
    float uk = (ax == 2) ? sn : 0.f;
    pr = cs * xr - ui * xi - uj * xj - uk * xk;
    pi = cs * xi + ui * xr + uj * xk - uk * xj;
    pj = cs * xj - ui * xk + uj * xr + uk * xi;
    pk = cs * xk + ui * xj - uj * xi + uk * xr;
}

// ---------------- build all 4 effective quaternion weights (fp16) ----------
struct WPtrs { const float* w[4][4]; };   // [proj][comp r,i,j,k]
__global__ void build_w_all_kernel(WPtrs wp, __half* __restrict__ WBase) {
    int proj = blockIdx.y;
    int idx = blockIdx.x * blockDim.x + threadIdx.x;   // 0 .. DIM*IQ-1
    int n = idx >> 8;          // 0..1023
    int p = idx & 255;         // 0..255
    int m = n >> 2, c = n & 3;

    int off = m * IQ + p;
    float r = wp.w[proj][0][off], i = wp.w[proj][1][off];
    float j = wp.w[proj][2][off], k = wp.w[proj][3][off];

    float v0, v1, v2, v3;
    switch (c) {
        case 0: v0 =  r; v1 = -i; v2 = -j; v3 = -k; break;
        case 1: v0 =  i; v1 =  r; v2 = -j; v3 =  k; break;
        case 2: v0 =  j; v1 =  i; v2 =  r; v3 = -k; break;
        default: v0 = k; v1 = -i; v2 =  j; v3 =  r; break;
    }

    size_t o = ((size_t)proj * DIM * DIM + (size_t)n * DIM + 4 * p) >> 2;
    ((uint2*)WBase)[o] = make_uint2(packf16(v0, v1), packf16(v2, v3));
}

// ---------------- convert fp32 activation into fp16 -------------------------
__global__ void cvt16_kernel(const float* __restrict__ in,
                             __half* __restrict__ out) {
    int i = blockIdx.x * blockDim.x + threadIdx.x;     // float4 index
    float4 v = ((const float4*)in)[i];
    ((uint2*)out)[i] = make_uint2(packf16(v.x, v.y), packf16(v.z, v.w));
}

// ================= fp16 single-product GEMM core ===========================
// C = A @ B^T, both fp16. Tile 128x128, 8 warps, K-slab 64, double buffered.
// smem per buffer (u32): A@0, B@4608; row stride 36 u32 (128B data + 16B pad).
#define SMS   36
#define BUFU  9216
#define GEMM_SMEM (2 * BUFU * 4)   /* 73728 */

__device__ __forceinline__ void gemm_core(
    const __half* pA, const __half* pB,
    uint32_t sbase, uint32_t* smu, uint32_t doff0, uint32_t rstep,
    int wm, int wn, int g, int t, float acc[4][4][4]) {

    // per slab: each thread copies 4 x 16B per matrix (rows tid>>3 + 32*i)
    #define ISSUE_SLAB(s, b) do {                                              \
        int _k0 = (s) * 64;                                                    \
        uint32_t _d = sbase + (uint32_t)(b) * (BUFU * 4) + doff0;              \
        cp_async16(_d,                  pA + _k0);                             \
        cp_async16(_d + rstep,          pA + _k0 + (size_t)32 * DIM);          \
        cp_async16(_d + 2 * rstep,      pA + _k0 + (size_t)64 * DIM);          \
        cp_async16(_d + 3 * rstep,      pA + _k0 + (size_t)96 * DIM);          \
        cp_async16(_d + 4608*4,             pB + _k0);                         \
        cp_async16(_d + 4608*4 + rstep,     pB + _k0 + (size_t)32 * DIM);      \
        cp_async16(_d + 4608*4 + 2 * rstep, pB + _k0 + (size_t)64 * DIM);      \
        cp_async16(_d + 4608*4 + 3 * rstep, pB + _k0 + (size_t)96 * DIM);      \
        CP_COMMIT();                                                           \
    } while (0)

    ISSUE_SLAB(0, 0);

    for (int s = 0; s < 16; s++) {
        const int cb = s & 1, nb = cb ^ 1;
        if (s + 1 < 16) {
            ISSUE_SLAB(s + 1, nb);
            CP_WAIT(1);
        } else {
            CP_WAIT(0);
        }
        __syncthreads();

        const uint32_t* base = smu + cb * BUFU;
        #pragma unroll
        for (int kk = 0; kk < 4; kk++) {
            uint32_t a[4][4];
            #pragma unroll
            for (int mi = 0; mi < 4; mi++) {
                int r0 = (wm * 64 + mi * 16 + g) * SMS + kk * 8 + t;
                a[mi][0] = base[r0];     a[mi][1] = base[r0 + 8 * SMS];
                a[mi][2] = base[r0 + 4]; a[mi][3] = base[r0 + 8 * SMS + 4];
            }
            uint32_t bb[4][2];
            #pragma unroll
            for (int nj = 0; nj < 4; nj++) {
                int rn = (wn * 32 + nj * 8 + g) * SMS + kk * 8 + t;
                bb[nj][0] = base[4608 + rn]; bb[nj][1] = base[4608 + rn + 4];
            }
            #pragma unroll
            for (int mi = 0; mi < 4; mi++)
                #pragma unroll
                for (int nj = 0; nj < 4; nj++)
                    mma16816h(acc[mi][nj], a[mi], bb[nj]);
        }
        __syncthreads();
    }
}

// z = 0: Q (rope + scale); 1: K (rope); 2: V (plain). All fp16 out.
__global__ __launch_bounds__(256) void qkv_gemm(
    const __half* __restrict__ A1, const __half* __restrict__ WBase,
    const float* __restrict__ q_b, const float* __restrict__ k_b,
    const float* __restrict__ v_b,
    __half* __restrict__ Q1, __half* __restrict__ K1, __half* __restrict__ V1) {
    extern __shared__ uint32_t smu[];
    const uint32_t sbase = smem_to_u32(smu);
    const int tid  = threadIdx.x;
    const int lane = tid & 31, wid = tid >> 5;
    const int g = lane >> 2, t = lane & 3;
    const int wm = wid & 1, wn = wid >> 1;
    const int bm = blockIdx.y * 128, bn = blockIdx.x * 128;
    const int z = blockIdx.z;

    const __half* B = WBase + (size_t)z * DIM * DIM;
    const float* bias = (z == 0) ? q_b : (z == 1) ? k_b : v_b;
    __half* C = (z == 0) ? Q1 : (z == 1) ? K1 : V1;

    float acc[4][4][4];
    #pragma unroll
    for (int i = 0; i < 4; i++)
        #pragma unroll
        for (int j = 0; j < 4; j++)
            #pragma unroll
            for (int q = 0; q < 4; q++) acc[i][j][q] = 0.f;

    const int crow0 = tid >> 3;          // 0..31
    const int ccol  = tid & 7;           // 16B chunk within 128B row
    gemm_core(A1 + (size_t)(bm + crow0) * DIM + ccol * 8,
              B  + (size_t)(bn + crow0) * DIM + ccol * 8,
              sbase, smu,
              (uint32_t)(crow0 * SMS + ccol * 4) * 4,
              (uint32_t)(32 * SMS) * 4,
              wm, wn, g, t, acc);

    if (z == 2) {
        // ---- V: plain fp16 ----
        #pragma unroll
        for (int mi = 0; mi < 4; mi++) {
            int row = bm + wm * 64 + mi * 16 + g;
            #pragma unroll
            for (int nj = 0; nj < 4; nj++) {
                int col = bn + wn * 32 + nj * 8 + 2 * t;
                float bx = bias[col], by = bias[col + 1];
                *(uint32_t*)&C[(size_t)row * DIM + col] =
                    packf16(acc[mi][nj][0] + bx, acc[mi][nj][1] + by);
                *(uint32_t*)&C[(size_t)(row + 8) * DIM + col] =
                    packf16(acc[mi][nj][2] + bx, acc[mi][nj][3] + by);
            }
        }
    } else {
        // ---- Q/K: fused RoPE; Q also folds softmax scale ----
        const bool evn = (t & 1) == 0;
        const float osc = (z == 0) ? QSCALE : 1.0f;
        #pragma unroll
        for (int nj = 0; nj < 4; nj++) {
            int col = bn + wn * 32 + nj * 8 + 2 * t;
            int grp = (col >> 2) & 15;
            float inv = powf(10000.0f, -(float)grp / 16.0f);
            int ax = grp % 3;
            float bx = bias[col], by = bias[col + 1];
            #pragma unroll
            for (int mi = 0; mi < 4; mi++) {
                int row = bm + wm * 64 + mi * 16 + g;
                float v0 = acc[mi][nj][0] + bx, v1 = acc[mi][nj][1] + by;
                float v2 = acc[mi][nj][2] + bx, v3 = acc[mi][nj][3] + by;
                float p0 = __shfl_xor_sync(0xFFFFFFFFu, v0, 1);
                float p1 = __shfl_xor_sync(0xFFFFFFFFu, v1, 1);
                float p2 = __shfl_xor_sync(0xFFFFFFFFu, v2, 1);
                float p3 = __shfl_xor_sync(0xFFFFFFFFu, v3, 1);
                #pragma unroll
                for (int half = 0; half < 2; half++) {
                    int r = row + 8 * half;
                    float a = (float)(r & 2047) * inv;
                    float cs = cosf(a), sn = sinf(a);
                    float a0 = half ? v2 : v0, a1 = half ? v3 : v1;
                    float b0 = half ? p2 : p0, b1 = half ? p3 : p1;
                    float xr, xi, xj, xk;
                    if (evn) { xr = a0; xi = a1; xj = b0; xk = b1; }
                    else     { xr = b0; xi = b1; xj = a0; xk = a1; }
                    float pr, pi, pj, pk;
                    qrot(cs, sn, ax, xr, xi, xj, xk, pr, pi, pj, pk);
                    float o0 = (evn ? pr : pj) * osc, o1 = (evn ? pi : pk) * osc;
                    *(uint32_t*)&C[(size_t)r * DIM + col] = packf16(o0, o1);
                }
            }
        }
    }
}

// ================= O-projection GEMM (fp32 out) ============================
__global__ __launch_bounds__(256) void o_gemm(
    const __half* __restrict__ A1, const __half* __restrict__ B,
    const float* __restrict__ bias, float* __restrict__ C) {
    extern __shared__ uint32_t smu[];
    const uint32_t sbase = smem_to_u32(smu);
    const int tid  = threadIdx.x;
    const int lane = tid & 31, wid = tid >> 5;
    const int g = lane >> 2, t = lane & 3;
    const int wm = wid & 1, wn = wid >> 1;
    const int bm = blockIdx.y * 128, bn = blockIdx.x * 128;

    float acc[4][4][4];
    #pragma unroll
    for (int i = 0; i < 4; i++)
        #pragma unroll
        for (int j = 0; j < 4; j++)
            #pragma unroll
            for (int q = 0; q < 4; q++) acc[i][j][q] = 0.f;

    const int crow0 = tid >> 3;
    const int ccol  = tid & 7;
    gemm_core(A1 + (size_t)(bm + crow0) * DIM + ccol * 8,
              B  + (size_t)(bn + crow0) * DIM + ccol * 8,
              sbase, smu,
              (uint32_t)(crow0 * SMS + ccol * 4) * 4,
              (uint32_t)(32 * SMS) * 4,
              wm, wn, g, t, acc);

    #pragma unroll
    for (int mi = 0; mi < 4; mi++) {
        int row = bm + wm * 64 + mi * 16 + g;
        #pragma unroll
        for (int nj = 0; nj < 4; nj++) {
            int col = bn + wn * 32 + nj * 8 + 2 * t;
            float bx = bias[col], by = bias[col + 1];
            float2 v;
            v.x = acc[mi][nj][0] + bx; v.y = acc[mi][nj][1] + by;
            *(float2*)&C[(size_t)row * DIM + col] = v;
            v.x = acc[mi][nj][2] + bx; v.y = acc[mi][nj][3] + by;
            *(float2*)&C[(size_t)(row + 8) * DIM + col] = v;
        }
    }
}

// ================= tensor-core causal flash attention ======================
// 128q x 64k tiles, 8 warps, fp16 single product, 2-stage KV double buffer,
// 2 CTAs/SM, x4-batched LDSM, packed f16x2 softmax exp.
// Stage (18432B): K@0, V@9216; 144B rows.
#define ATT_STRIDE 144
#define ATT_STAGE  18432
#define ATT_SMEM   (2 * ATT_STAGE)      /* 36864 */
__global__ __launch_bounds__(256, 2) void attn_tc(
    const __half* __restrict__ Q1,
    const __half* __restrict__ K1, const __half* __restrict__ V1,
    __half* __restrict__ O1) {
    extern __shared__ __align__(16) char sm[];
    const uint32_t sb = smem_to_u32(sm);
    const int tid = threadIdx.x, lane = tid & 31, wid = tid >> 5;
    const int g = lane >> 2, t = lane & 3;
    const int qt = (int)gridDim.x - 1 - (int)blockIdx.x;   // heavy blocks first
    const int bh = blockIdx.y;
    const int b = bh >> 4, h = bh & 15;
    const int qb = qt * 128;
    const size_t rbase = (size_t)b * SQ;
    const int hoff = h * DH;

    // ---- stage Q tile, extract fragments to regs ----
    #pragma unroll
    for (int i = 0; i < 4; i++) {
        int rem = tid + 256 * i;              // 0..1023
        int r = rem >> 3, c = rem & 7;
        cp_async16(sb + r * ATT_STRIDE + c * 16,
                   Q1 + (rbase + qb + r) * DIM + hoff + c * 8);
    }
    CP_COMMIT(); CP_WAIT(0);
    __syncthreads();

    uint32_t qf[4][4];
    {
        uint32_t abase = sb + (wid * 16 + (lane & 15)) * ATT_STRIDE + (lane >> 4) * 16;
        #pragma unroll
        for (int kc = 0; kc < 4; kc++)
            ldmatrix_x4(qf[kc], abase + kc * 32);
    }
    __syncthreads();

    float Oa[8][4];
    #pragma unroll
    for (int j = 0; j < 8; j++)
        #pragma unroll
        for (int e = 0; e < 4; e++) Oa[j][e] = 0.f;
    float m0 = -1e30f, m1 = -1e30f, l0 = 0.f, l1 = 0.f;
    const int r0 = qb + wid * 16 + g;
    const int ntiles = 2 * qt + 2;

    const __half* kvK = K1 + rbase * DIM + hoff;
    const __half* kvV = V1 + rbase * DIM + hoff;

    #define ISSUE_KV(jt_, st_) do {                                             \
        int _kb = (jt_) * 64;                                                   \
        uint32_t _s = sb + (uint32_t)(st_) * ATT_STAGE;                         \
        _Pragma("unroll")                                                       \
        for (int i = 0; i < 4; i++) {                                           \
            int rem = (i & 1) ? tid + 256 : tid;                                \
            int r = rem >> 3, c = rem & 7;                                      \
            const __half* src = (i >> 1) == 0 ? kvK : kvV;                      \
            cp_async16(_s + (i >> 1) * 9216 + r * ATT_STRIDE + c * 16,          \
                       src + (size_t)(_kb + r) * DIM + c * 8);                  \
        }                                                                       \
        CP_COMMIT();                                                            \
    } while (0)

    ISSUE_KV(0, 0);

    // lane sub-addresses for x4 K / x4-trans V loads (2 j per LDSM)
    const uint32_t krow = (uint32_t)((lane & 7) + ((lane >> 4) << 3));
    const uint32_t kcolh = (uint32_t)(((lane >> 3) & 1) * 16);
    const uint32_t vrow = (uint32_t)((lane & 7) + (((lane >> 3) & 1) << 3));
    const uint32_t vcol = (uint32_t)((lane >> 4) & 1);

    for (int jt = 0; jt < ntiles; jt++) {
        const int kb = jt * 64;
        const int cb = jt & 1, nb = cb ^ 1;
        if (jt + 1 < ntiles) {
            ISSUE_KV(jt + 1, nb);
            CP_WAIT(1);
        } else {
            CP_WAIT(0);
        }
        __syncthreads();
        const uint32_t stg = sb + (uint32_t)cb * ATT_STAGE;

        // ---- S = Q K^T : single product, x4 K loads (j pairs) ----
        float S[8][4];
        #pragma unroll
        for (int j = 0; j < 8; j++)
            #pragma unroll
            for (int e = 0; e < 4; e++) S[j][e] = 0.f;

        #pragma unroll
        for (int kc = 0; kc < 4; kc++) {
            uint32_t kaddr = stg + krow * ATT_STRIDE + kc * 32 + kcolh;
            #pragma unroll
            for (int j = 0; j < 8; j += 2) {
                uint32_t bk[4];
                ldmatrix_x4(bk, kaddr + j * 8 * ATT_STRIDE);
                mma16816h(S[j],     qf[kc], bk + 0);
                mma16816h(S[j + 1], qf[kc], bk + 2);
            }
        }

        // ---- causal mask (S already scaled via Q) ----
        if (kb + 63 > qb) {
            #pragma unroll
            for (int j = 0; j < 8; j++) {
                int k0 = kb + 8 * j + 2 * t;
                if (k0     > r0    ) S[j][0] = -1e30f;
                if (k0 + 1 > r0    ) S[j][1] = -1e30f;
                if (k0     > r0 + 8) S[j][2] = -1e30f;
                if (k0 + 1 > r0 + 8) S[j][3] = -1e30f;
            }
        }

        // ---- online softmax (log2 domain), exp in packed f16x2 ----
        float tm0 = -1e30f, tm1 = -1e30f;
        #pragma unroll
        for (int j = 0; j < 8; j++) {
            tm0 = fmaxf(tm0, fmaxf(S[j][0], S[j][1]));
            tm1 = fmaxf(tm1, fmaxf(S[j][2], S[j][3]));
        }
        tm0 = fmaxf(tm0, __shfl_xor_sync(0xFFFFFFFFu, tm0, 1));
        tm0 = fmaxf(tm0, __shfl_xor_sync(0xFFFFFFFFu, tm0, 2));
        tm1 = fmaxf(tm1, __shfl_xor_sync(0xFFFFFFFFu, tm1, 1));
        tm1 = fmaxf(tm1, __shfl_xor_sync(0xFFFFFFFFu, tm1, 2));
        float mn0 = fmaxf(m0, tm0), mn1 = fmaxf(m1, tm1);
        float sc0 = ex2f(m0 - mn0), sc1 = ex2f(m1 - mn1);
        m0 = mn0; m1 = mn1;
        l0 *= sc0; l1 *= sc1;
        #pragma unroll
        for (int j = 0; j < 8; j++) {
            Oa[j][0] *= sc0; Oa[j][1] *= sc0;
            Oa[j][2] *= sc1; Oa[j][3] *= sc1;
        }

        uint32_t P2[8][2];
        #pragma unroll
        for (int j = 0; j < 8; j++) {
            P2[j][0] = ex2h2(packf16(S[j][0] - mn0, S[j][1] - mn0));
            P2[j][1] = ex2h2(packf16(S[j][2] - mn1, S[j][3] - mn1));
            float2 f0 = unpackf16(P2[j][0]);
            float2 f1 = unpackf16(P2[j][1]);
            l0 += f0.x + f0.y;
            l1 += f1.x + f1.y;
        }

        // ---- O += P V : single product, P already packed ----
        #pragma unroll
        for (int c = 0; c < 4; c++) {
            uint32_t pa[4];
            pa[0] = P2[2*c  ][0];
            pa[1] = P2[2*c  ][1];
            pa[2] = P2[2*c+1][0];
            pa[3] = P2[2*c+1][1];
            uint32_t vbase = stg + 9216 + (16 * c + vrow) * ATT_STRIDE;
            #pragma unroll
            for (int j = 0; j < 8; j += 2) {
                uint32_t bv[4];
                ldmatrix_x4_trans(bv, vbase + (j + vcol) * 16);
                mma16816h(Oa[j],     pa, bv + 0);
                mma16816h(Oa[j + 1], pa, bv + 2);
            }
        }
        __syncthreads();
    }

    // ---- finalize: write fp16 ----
    l0 += __shfl_xor_sync(0xFFFFFFFFu, l0, 1);
    l0 += __shfl_xor_sync(0xFFFFFFFFu, l0, 2);
    l1 += __shfl_xor_sync(0xFFFFFFFFu, l1, 1);
    l1 += __shfl_xor_sync(0xFFFFFFFFu, l1, 2);
    float inv0 = 1.f / l0, inv1 = 1.f / l1;
    size_t off0 = (rbase + r0) * DIM + hoff + 2 * t;
    size_t off1 = (rbase + r0 + 8) * DIM + hoff + 2 * t;
    #pragma unroll
    for (int j = 0; j < 8; j++) {
        *(uint32_t*)&O1[off0 + 8 * j] = packf16(Oa[j][0] * inv0, Oa[j][1] * inv0);
        *(uint32_t*)&O1[off1 + 8 * j] = packf16(Oa[j][2] * inv1, Oa[j][3] * inv1);
    }
}

// ---------------- launch ---------------------------------------------------
extern "C" void kernel_launch(void* const* d_in, const int* in_sizes, int n_in,
                              void* d_out, int out_size) {
    const float* x = (const float*)d_in[0];
    // d_in[1] = mask (pure causal triu, ignored)
    const float* q_b = (const float*)d_in[6];
    const float* k_b = (const float*)d_in[11];
    const float* v_b = (const float*)d_in[16];
    const float* o_b = (const float*)d_in[21];

    WPtrs wp;
    for (int pr = 0; pr < 4; pr++)
        for (int cm = 0; cm < 4; cm++)
            wp.w[pr][cm] = (const float*)d_in[2 + 5 * pr + cm];

    __half *w1, *a1, *q1, *k1, *v1;
    cudaGetSymbolAddress((void**)&w1, g_w1);
    cudaGetSymbolAddress((void**)&a1, g_a1);
    cudaGetSymbolAddress((void**)&q1, g_q1);
    cudaGetSymbolAddress((void**)&k1, g_k1);
    cudaGetSymbolAddress((void**)&v1, g_v1);

    cudaFuncSetAttribute(qkv_gemm, cudaFuncAttributeMaxDynamicSharedMemorySize,
                         GEMM_SMEM);
    cudaFuncSetAttribute(o_gemm, cudaFuncAttributeMaxDynamicSharedMemorySize,
                         GEMM_SMEM);
    cudaFuncSetAttribute(attn_tc, cudaFuncAttributeMaxDynamicSharedMemorySize,
                         ATT_SMEM);

    dim3 wgrid((DIM * IQ) / 256, 4);
    build_w_all_kernel<<<wgrid, 256>>>(wp, w1);

    const int sblocks = (MROW * DIM / 4) / 256;
    cvt16_kernel<<<sblocks, 256>>>(x, a1);

    dim3 qkvgrid(DIM / 128, MROW / 128, 3);    // (8, 32, 3)
    qkv_gemm<<<qkvgrid, 256, GEMM_SMEM>>>(a1, w1, q_b, k_b, v_b, q1, k1, v1);

    dim3 agrid(SQ / 128, BQ * HQ);             // (16, 32)
    attn_tc<<<agrid, 256, ATT_SMEM>>>(q1, k1, v1, a1);

    dim3 ogrid(DIM / 128, MROW / 128);         // (8, 32)
    o_gemm<<<ogrid, 256, GEMM_SMEM>>>(a1, w1 + 3 * (size_t)DIM * DIM,
                                      o_b, (float*)d_out);
}